// round 11
// baseline (speedup 1.0000x reference)
#include <cuda_runtime.h>
#include <cuda_bf16.h>
#include <cstdint>

// ---------------- problem constants ----------------
#define NNODES 50000
#define NEDGES 800000
#define PCTA   148
#define PTHR   512
#define PGTH   (PCTA * PTHR)            // 75776
#define CH     338                      // nodes per CTA chunk (148*338 >= 50000)

// ---------------- device scratch (no allocs allowed) ----------------
__device__ int      g_src[NEDGES];
__device__ int      g_dst[NEDGES];
__device__ int      g_deg[NNODES];
__device__ int      g_rowptr[NNODES + 1];
__device__ int      g_fill[NNODES];
__device__ int      g_csrc[NEDGES];
__device__ int      g_bsum[PCTA];
__device__ float    g_dinv[NNODES];
__device__ uint2    g_zb[NNODES * 32];   // z bf16: 128 cols = 32 uint2
__device__ float    g_y[NNODES * 128];
__device__ float    g_h[NNODES * 128];
__device__ unsigned g_barcnt;
__device__ unsigned g_bargen;

__device__ __forceinline__ float to_tf32(float x) {
    float r;
    asm("cvt.rna.tf32.f32 %0, %1;" : "=f"(r) : "f"(x));
    return r;
}

// sense-reversing grid barrier; safe: 148 CTAs, 512 thr, 4KB smem -> co-resident
__device__ __forceinline__ void gsync() {
    __syncthreads();
    if (threadIdx.x == 0) {
        __threadfence();
        unsigned gen = *(volatile unsigned*)&g_bargen;
        if (atomicAdd(&g_barcnt, 1u) == PCTA - 1) {
            g_barcnt = 0;
            __threadfence();
            *(volatile unsigned*)&g_bargen = gen + 1;
        } else {
            while (*(volatile unsigned*)&g_bargen == gen) { }
        }
        __threadfence();
    }
    __syncthreads();
}

// ---------------- fused prep: zero + decode + scan + fill ----------------
__global__ __launch_bounds__(PTHR, 1)
void k_prep(const void* __restrict__ ei_raw) {
    __shared__ int sscan[PTHR];
    __shared__ int sred[PTHR];
    const int tid  = threadIdx.x;
    const int cta  = blockIdx.x;
    const int gtid = cta * PTHR + tid;

    // P0: zero deg/fill
    for (int i = gtid; i < NNODES; i += PGTH) { g_deg[i] = 0; g_fill[i] = 0; }
    gsync();

    // P1: dtype detect (broadcast loads, uniform branch) + decode + degree
    const long long* e64 = (const long long*)ei_raw;
    bool is32 = false;
    #pragma unroll
    for (int q = 0; q < 4; ++q) {
        long long v = e64[q];
        if (v < 0 || v >= NNODES) is32 = true;
    }
    if (is32) {
        const int* e = (const int*)ei_raw;
        for (int i = gtid; i < NEDGES; i += PGTH) {
            int d = e[i], s = e[NEDGES + i];
            g_dst[i] = d; g_src[i] = s;
            atomicAdd(&g_deg[d], 1);
        }
    } else {
        for (int i = gtid; i < NEDGES; i += PGTH) {
            int d = (int)e64[i], s = (int)e64[NEDGES + i];
            g_dst[i] = d; g_src[i] = s;
            atomicAdd(&g_deg[d], 1);
        }
    }
    gsync();

    // P2: per-CTA inclusive scan of its CH-node chunk
    const int base = cta * CH;
    {
        int v = 0;
        if (tid < CH && base + tid < NNODES) v = g_deg[base + tid];
        sscan[tid] = v;
        __syncthreads();
        #pragma unroll
        for (int off = 1; off < PTHR; off <<= 1) {
            int t = (tid >= off) ? sscan[tid - off] : 0;
            __syncthreads();
            sscan[tid] += t;
            __syncthreads();
        }
        if (tid == PTHR - 1) g_bsum[cta] = sscan[tid];
    }
    gsync();

    // P3: global offset (reduce bsum[0..cta)) + write rowptr/dinv
    {
        int p = (tid < cta) ? g_bsum[tid] : 0;   // cta < 148 < 512
        sred[tid] = p;
        __syncthreads();
        #pragma unroll
        for (int off = PTHR / 2; off > 0; off >>= 1) {
            if (tid < off) sred[tid] += sred[tid + off];
            __syncthreads();
        }
        int offset = sred[0];
        if (cta == 0 && tid == 0) g_rowptr[0] = 0;
        if (tid < CH && base + tid < NNODES) {
            g_rowptr[base + tid + 1] = sscan[tid] + offset;
            g_dinv[base + tid] = 1.0f / fmaxf((float)g_deg[base + tid], 1.0f);
        }
    }
    gsync();

    // P4: CSR fill
    for (int i = gtid; i < NEDGES; i += PGTH) {
        int d = g_dst[i];
        int pos = g_rowptr[d] + atomicAdd(&g_fill[d], 1);
        g_csrc[pos] = g_src[i];
    }
}

// ---------------- mma.sync tf32 dual GEMM (unchanged from R10) ------------
template <int NC>
__global__ __launch_bounds__(512, 1)
void k_gemm_mma(const float* __restrict__ H,
                const float* __restrict__ Wl, const float* __restrict__ Wr,
                __nv_bfloat162* __restrict__ Zb, float* __restrict__ Y) {
    constexpr int D   = NC / 2;
    constexpr int NT  = NC / 32;
    constexpr int ST  = 132;

    extern __shared__ float smem[];
    float* sA = smem;
    float* sB = smem + 128 * ST;

    const int tid  = threadIdx.x;
    const int wid  = tid >> 5;
    const int lane = tid & 31;
    const int row0 = blockIdx.x * 128;

    {
        const float4* h4 = (const float4*)H;
        #pragma unroll
        for (int i = tid; i < 128 * 32; i += 512) {
            int r = i >> 5, c = i & 31;
            int gr = row0 + r;
            float4 v = make_float4(0.f, 0.f, 0.f, 0.f);
            if (gr < NNODES) v = h4[gr * 32 + c];
            float* p = &sA[r * ST + c * 4];
            p[0] = to_tf32(v.x); p[1] = to_tf32(v.y);
            p[2] = to_tf32(v.z); p[3] = to_tf32(v.w);
        }
    }
    {
        #pragma unroll
        for (int i = tid; i < NC * 32; i += 512) {
            int n = i >> 5, c = i & 31;
            const float4* wsrc = (const float4*)((n < D) ? (Wl + n * 128)
                                                         : (Wr + (n - D) * 128));
            float4 v = wsrc[c];
            float* p = &sB[n * ST + c * 4];
            p[0] = to_tf32(v.x); p[1] = to_tf32(v.y);
            p[2] = to_tf32(v.z); p[3] = to_tf32(v.w);
        }
    }
    __syncthreads();

    const int warp_m = wid & 3;
    const int warp_n = wid >> 2;
    const int lm = lane >> 2;
    const int lk = lane & 3;

    float acc[2][NT][4];
    #pragma unroll
    for (int mi = 0; mi < 2; ++mi)
        #pragma unroll
        for (int ni = 0; ni < NT; ++ni)
            #pragma unroll
            for (int q = 0; q < 4; ++q) acc[mi][ni][q] = 0.f;

    #pragma unroll
    for (int kk = 0; kk < 16; ++kk) {
        const int k0 = kk * 8;
        uint32_t a[2][4];
        #pragma unroll
        for (int mi = 0; mi < 2; ++mi) {
            const int rb = warp_m * 32 + mi * 16;
            a[mi][0] = *(const uint32_t*)&sA[(rb + lm)     * ST + k0 + lk];
            a[mi][1] = *(const uint32_t*)&sA[(rb + 8 + lm) * ST + k0 + lk];
            a[mi][2] = *(const uint32_t*)&sA[(rb + lm)     * ST + k0 + 4 + lk];
            a[mi][3] = *(const uint32_t*)&sA[(rb + 8 + lm) * ST + k0 + 4 + lk];
        }
        uint32_t b[NT][2];
        #pragma unroll
        for (int ni = 0; ni < NT; ++ni) {
            const int nb = warp_n * (NT * 8) + ni * 8;
            b[ni][0] = *(const uint32_t*)&sB[(nb + lm) * ST + k0 + lk];
            b[ni][1] = *(const uint32_t*)&sB[(nb + lm) * ST + k0 + 4 + lk];
        }
        #pragma unroll
        for (int mi = 0; mi < 2; ++mi)
            #pragma unroll
            for (int ni = 0; ni < NT; ++ni) {
                asm volatile(
                    "mma.sync.aligned.m16n8k8.row.col.f32.tf32.tf32.f32 "
                    "{%0,%1,%2,%3}, {%4,%5,%6,%7}, {%8,%9}, {%0,%1,%2,%3};"
                    : "+f"(acc[mi][ni][0]), "+f"(acc[mi][ni][1]),
                      "+f"(acc[mi][ni][2]), "+f"(acc[mi][ni][3])
                    : "r"(a[mi][0]), "r"(a[mi][1]), "r"(a[mi][2]), "r"(a[mi][3]),
                      "r"(b[ni][0]), "r"(b[ni][1]));
            }
    }

    {
        const bool yhalf = (warp_n >= 2);
        const int cbase = warp_n * (NT * 8) - (yhalf ? D : 0);
        #pragma unroll
        for (int mi = 0; mi < 2; ++mi) {
            const int rl = row0 + warp_m * 32 + mi * 16 + lm;
            const int rh = rl + 8;
            #pragma unroll
            for (int ni = 0; ni < NT; ++ni) {
                const int oc = cbase + ni * 8 + lk * 2;
                if (yhalf) {
                    if (rl < NNODES)
                        *(float2*)&Y[rl * D + oc] = make_float2(acc[mi][ni][0], acc[mi][ni][1]);
                    if (rh < NNODES)
                        *(float2*)&Y[rh * D + oc] = make_float2(acc[mi][ni][2], acc[mi][ni][3]);
                } else {
                    if (rl < NNODES)
                        Zb[rl * (D / 2) + oc / 2] =
                            __float22bfloat162_rn(make_float2(acc[mi][ni][0], acc[mi][ni][1]));
                    if (rh < NNODES)
                        Zb[rh * (D / 2) + oc / 2] =
                            __float22bfloat162_rn(make_float2(acc[mi][ni][2], acc[mi][ni][3]));
                }
            }
        }
    }
}

// -------- gather + combine + relu (D=128): warp/node, 4-wide MLP ----------
__global__ __launch_bounds__(256)
void k_gather_combine128(const uint2* __restrict__ Zb, const float* __restrict__ Yb,
                         const float* __restrict__ bias, float* __restrict__ Hout) {
    const int w    = (blockIdx.x * blockDim.x + threadIdx.x) >> 5;
    const int lane = threadIdx.x & 31;
    if (w >= NNODES) return;
    int j = g_rowptr[w];
    const int e = g_rowptr[w + 1];
    float4 a0 = make_float4(0.f, 0.f, 0.f, 0.f);
    float4 a1 = make_float4(0.f, 0.f, 0.f, 0.f);
    float4 a2 = make_float4(0.f, 0.f, 0.f, 0.f);
    float4 a3 = make_float4(0.f, 0.f, 0.f, 0.f);
    for (; j + 3 < e; j += 4) {
        int s0 = g_csrc[j];
        int s1 = g_csrc[j + 1];
        int s2 = g_csrc[j + 2];
        int s3 = g_csrc[j + 3];
        uint2 u0 = Zb[s0 * 32 + lane];
        uint2 u1 = Zb[s1 * 32 + lane];
        uint2 u2 = Zb[s2 * 32 + lane];
        uint2 u3 = Zb[s3 * 32 + lane];
        float2 f;
        f = __bfloat1622float2(*(const __nv_bfloat162*)&u0.x); a0.x += f.x; a0.y += f.y;
        f = __bfloat1622float2(*(const __nv_bfloat162*)&u0.y); a0.z += f.x; a0.w += f.y;
        f = __bfloat1622float2(*(const __nv_bfloat162*)&u1.x); a1.x += f.x; a1.y += f.y;
        f = __bfloat1622float2(*(const __nv_bfloat162*)&u1.y); a1.z += f.x; a1.w += f.y;
        f = __bfloat1622float2(*(const __nv_bfloat162*)&u2.x); a2.x += f.x; a2.y += f.y;
        f = __bfloat1622float2(*(const __nv_bfloat162*)&u2.y); a2.z += f.x; a2.w += f.y;
        f = __bfloat1622float2(*(const __nv_bfloat162*)&u3.x); a3.x += f.x; a3.y += f.y;
        f = __bfloat1622float2(*(const __nv_bfloat162*)&u3.y); a3.z += f.x; a3.w += f.y;
    }
    for (; j < e; ++j) {
        int s0 = g_csrc[j];
        uint2 u0 = Zb[s0 * 32 + lane];
        float2 f;
        f = __bfloat1622float2(*(const __nv_bfloat162*)&u0.x); a0.x += f.x; a0.y += f.y;
        f = __bfloat1622float2(*(const __nv_bfloat162*)&u0.y); a0.z += f.x; a0.w += f.y;
    }
    a0.x += a1.x + a2.x + a3.x;
    a0.y += a1.y + a2.y + a3.y;
    a0.z += a1.z + a2.z + a3.z;
    a0.w += a1.w + a2.w + a3.w;
    float inv = g_dinv[w];
    float4 yv = ((const float4*)Yb)[w * 32 + lane];
    float4 bv = ((const float4*)bias)[lane];
    float4 o;
    o.x = fmaxf(a0.x * inv + yv.x + bv.x, 0.f);
    o.y = fmaxf(a0.y * inv + yv.y + bv.y, 0.f);
    o.z = fmaxf(a0.z * inv + yv.z + bv.z, 0.f);
    o.w = fmaxf(a0.w * inv + yv.w + bv.w, 0.f);
    ((float4*)Hout)[w * 32 + lane] = o;
}

// -------- gather + combine + log_softmax (D=64): 4-wide MLP --------
__global__ __launch_bounds__(256)
void k_gather_final64(const unsigned* __restrict__ Zb, const float* __restrict__ Yb,
                      const float* __restrict__ bias, float* __restrict__ out) {
    const int w    = (blockIdx.x * blockDim.x + threadIdx.x) >> 5;
    const int lane = threadIdx.x & 31;
    if (w >= NNODES) return;
    int j = g_rowptr[w];
    const int e = g_rowptr[w + 1];
    float2 a0 = make_float2(0.f, 0.f);
    float2 a1 = make_float2(0.f, 0.f);
    float2 a2 = make_float2(0.f, 0.f);
    float2 a3 = make_float2(0.f, 0.f);
    for (; j + 3 < e; j += 4) {
        int s0 = g_csrc[j];
        int s1 = g_csrc[j + 1];
        int s2 = g_csrc[j + 2];
        int s3 = g_csrc[j + 3];
        unsigned u0 = Zb[s0 * 32 + lane];
        unsigned u1 = Zb[s1 * 32 + lane];
        unsigned u2 = Zb[s2 * 32 + lane];
        unsigned u3 = Zb[s3 * 32 + lane];
        float2 f;
        f = __bfloat1622float2(*(const __nv_bfloat162*)&u0); a0.x += f.x; a0.y += f.y;
        f = __bfloat1622float2(*(const __nv_bfloat162*)&u1); a1.x += f.x; a1.y += f.y;
        f = __bfloat1622float2(*(const __nv_bfloat162*)&u2); a2.x += f.x; a2.y += f.y;
        f = __bfloat1622float2(*(const __nv_bfloat162*)&u3); a3.x += f.x; a3.y += f.y;
    }
    for (; j < e; ++j) {
        int s0 = g_csrc[j];
        unsigned u0 = Zb[s0 * 32 + lane];
        float2 f = __bfloat1622float2(*(const __nv_bfloat162*)&u0);
        a0.x += f.x; a0.y += f.y;
    }
    a0.x += a1.x + a2.x + a3.x;
    a0.y += a1.y + a2.y + a3.y;
    float inv = g_dinv[w];
    float2 yv = ((const float2*)Yb)[w * 32 + lane];
    float2 bv = ((const float2*)bias)[lane];
    float v0 = a0.x * inv + yv.x + bv.x;
    float v1 = a0.y * inv + yv.y + bv.y;
    float m = fmaxf(v0, v1);
    #pragma unroll
    for (int o = 16; o; o >>= 1) m = fmaxf(m, __shfl_xor_sync(0xffffffffu, m, o));
    float s = expf(v0 - m) + expf(v1 - m);
    #pragma unroll
    for (int o = 16; o; o >>= 1) s += __shfl_xor_sync(0xffffffffu, s, o);
    float lse = m + logf(s);
    out[w * 64 + lane * 2 + 0] = v0 - lse;
    out[w * 64 + lane * 2 + 1] = v1 - lse;
}

// ---------------- host launch ----------------
extern "C" void kernel_launch(void* const* d_in, const int* in_sizes, int n_in,
                              void* d_out, int out_size) {
    const float* x   = (const float*)d_in[0];
    const void*  ei  = d_in[1];
    const float* Wl0 = (const float*)d_in[2];
    const float* bl0 = (const float*)d_in[3];
    const float* Wr0 = (const float*)d_in[4];
    const float* Wl1 = (const float*)d_in[5];
    const float* bl1 = (const float*)d_in[6];
    const float* Wr1 = (const float*)d_in[7];
    const float* Wl2 = (const float*)d_in[8];
    const float* bl2 = (const float*)d_in[9];
    const float* Wr2 = (const float*)d_in[10];
    float* out = (float*)d_out;
    (void)in_sizes; (void)n_in; (void)out_size;

    void *p_zb, *p_y, *p_h;
    cudaGetSymbolAddress(&p_zb, g_zb);
    cudaGetSymbolAddress(&p_y,  g_y);
    cudaGetSymbolAddress(&p_h,  g_h);

    const int SM256 = (128 * 132 + 256 * 132) * 4;
    const int SM128 = (128 * 132 + 128 * 132) * 4;
    cudaFuncSetAttribute(k_gemm_mma<256>, cudaFuncAttributeMaxDynamicSharedMemorySize, SM256);
    cudaFuncSetAttribute(k_gemm_mma<128>, cudaFuncAttributeMaxDynamicSharedMemorySize, SM128);

    const int GT = (NNODES + 127) / 128;
    const int GW = (NNODES * 32 + 255) / 256;

    // layer-0 GEMM (edge-independent)
    k_gemm_mma<256><<<GT, 512, SM256>>>(x, Wl0, Wr0, (__nv_bfloat162*)p_zb, (float*)p_y);

    // fused prep: zero + decode + degree + scan + offsets + CSR fill
    k_prep<<<PCTA, PTHR>>>(ei);

    // ---- layer 0 combine ----
    k_gather_combine128<<<GW, 256>>>((const uint2*)p_zb, (const float*)p_y, bl0, (float*)p_h);

    // ---- layer 1 ----
    k_gemm_mma<256><<<GT, 512, SM256>>>((const float*)p_h, Wl1, Wr1,
                                        (__nv_bfloat162*)p_zb, (float*)p_y);
    k_gather_combine128<<<GW, 256>>>((const uint2*)p_zb, (const float*)p_y, bl1, (float*)p_h);

    // ---- layer 2 + log_softmax ----
    k_gemm_mma<128><<<GT, 512, SM128>>>((const float*)p_h, Wl2, Wr2,
                                        (__nv_bfloat162*)p_zb, (float*)p_y);
    k_gather_final64<<<GW, 256>>>((const unsigned*)p_zb, (const float*)p_y, bl2, out);
}

// round 12
// speedup vs baseline: 1.2064x; 1.2064x over previous
#include <cuda_runtime.h>
#include <cuda_bf16.h>
#include <cstdint>

// ---------------- problem constants ----------------
#define NNODES 50000
#define NEDGES 800000
#define SCAN_B 256
#define NBLK   ((NNODES + SCAN_B - 1) / SCAN_B)   // 196

// ---------------- device scratch (no allocs allowed) ----------------
__device__ int   g_src[NEDGES];
__device__ int   g_dst[NEDGES];
__device__ int   g_deg[NNODES];
__device__ int   g_rowptr[NNODES + 1];
__device__ int   g_fill[NNODES];
__device__ int   g_csrc[NEDGES];
__device__ int   g_bsum[NBLK];
__device__ float g_dinv[NNODES];
__device__ uint2 g_zb[NNODES * 32];     // z bf16: 128 cols = 32 uint2
__device__ float g_y[NNODES * 128];
__device__ float g_h[NNODES * 128];

__device__ __forceinline__ uint32_t pack_bf2(float x, float y) {
    __nv_bfloat162 t = __float22bfloat162_rn(make_float2(x, y));
    return *(uint32_t*)&t;
}

// ---------------- edge decode + degree (dtype detected inline) ----------
__global__ void k_prep_edges(const void* __restrict__ ei_raw) {
    int i = blockIdx.x * blockDim.x + threadIdx.x;
    if (i >= NEDGES) return;
    const long long* e64 = (const long long*)ei_raw;
    bool is32 = false;
    #pragma unroll
    for (int q = 0; q < 4; ++q) {
        long long v = e64[q];
        if (v < 0 || v >= NNODES) is32 = true;
    }
    int d, s;
    if (is32) {
        const int* e = (const int*)ei_raw;
        d = e[i]; s = e[NEDGES + i];
    } else {
        d = (int)e64[i]; s = (int)e64[NEDGES + i];
    }
    g_dst[i] = d;
    g_src[i] = s;
    atomicAdd(&g_deg[d], 1);
}

// ---------------- CSR build ----------------
__global__ void k_scan1() {
    __shared__ int s[SCAN_B];
    int tid = threadIdx.x;
    int i = blockIdx.x * SCAN_B + tid;
    int v = (i < NNODES) ? g_deg[i] : 0;
    s[tid] = v;
    __syncthreads();
    #pragma unroll
    for (int off = 1; off < SCAN_B; off <<= 1) {
        int t = (tid >= off) ? s[tid - off] : 0;
        __syncthreads();
        s[tid] += t;
        __syncthreads();
    }
    if (i < NNODES) g_rowptr[i + 1] = s[tid];
    if (tid == SCAN_B - 1) g_bsum[blockIdx.x] = s[tid];
}

__global__ void k_scan3() {
    __shared__ int red[SCAN_B];
    int tid = threadIdx.x;
    int part = (tid < (int)blockIdx.x && tid < NBLK) ? g_bsum[tid] : 0;
    red[tid] = part;
    __syncthreads();
    #pragma unroll
    for (int off = SCAN_B / 2; off > 0; off >>= 1) {
        if (tid < off) red[tid] += red[tid + off];
        __syncthreads();
    }
    int offset = red[0];
    int i = blockIdx.x * SCAN_B + tid;
    if (i == 0) g_rowptr[0] = 0;
    if (i < NNODES) {
        g_rowptr[i + 1] += offset;
        g_dinv[i] = 1.0f / fmaxf((float)g_deg[i], 1.0f);
    }
}
__global__ void k_fill() {
    int i = blockIdx.x * blockDim.x + threadIdx.x;
    if (i >= NEDGES) return;
    int d = g_dst[i];
    int pos = g_rowptr[d] + atomicAdd(&g_fill[d], 1);
    g_csrc[pos] = g_src[i];
}

// ---------------- mma.sync bf16 m16n8k16 dual GEMM ----------------
// D[128, NC] = A[128,128] @ B[NC,128]^T; operands bf16-packed in smem,
// fp32 accumulate. Z half stored bf16, Y half fp32. 512 threads.
template <int NC>
__global__ __launch_bounds__(512, 1)
void k_gemm_mma(const float* __restrict__ H,
                const float* __restrict__ Wl, const float* __restrict__ Wr,
                __nv_bfloat162* __restrict__ Zb, float* __restrict__ Y) {
    constexpr int D   = NC / 2;
    constexpr int NT  = NC / 32;        // n-frags per warp
    constexpr int STU = 68;             // row stride in uint32 (64 data + 4 pad)

    extern __shared__ uint32_t smem[];
    uint32_t* sA = smem;                // 128 x STU
    uint32_t* sB = smem + 128 * STU;    // NC x STU

    const int tid  = threadIdx.x;
    const int wid  = tid >> 5;
    const int lane = tid & 31;
    const int row0 = blockIdx.x * 128;

    // stage A: fp32 -> packed bf16 pairs
    {
        const float4* h4 = (const float4*)H;
        #pragma unroll
        for (int i = tid; i < 128 * 32; i += 512) {
            int r = i >> 5, c = i & 31;           // c = float4 index (2 uint32 out)
            int gr = row0 + r;
            float4 v = make_float4(0.f, 0.f, 0.f, 0.f);
            if (gr < NNODES) v = h4[gr * 32 + c];
            uint2 p = make_uint2(pack_bf2(v.x, v.y), pack_bf2(v.z, v.w));
            *(uint2*)&sA[r * STU + c * 2] = p;
        }
    }
    // stage B = [Wl ; Wr] rows
    {
        #pragma unroll
        for (int i = tid; i < NC * 32; i += 512) {
            int n = i >> 5, c = i & 31;
            const float4* wsrc = (const float4*)((n < D) ? (Wl + n * 128)
                                                         : (Wr + (n - D) * 128));
            float4 v = wsrc[c];
            uint2 p = make_uint2(pack_bf2(v.x, v.y), pack_bf2(v.z, v.w));
            *(uint2*)&sB[n * STU + c * 2] = p;
        }
    }
    __syncthreads();

    const int warp_m = wid & 3;         // 32-row band
    const int warp_n = wid >> 2;        // NC/4-col band
    const int lm = lane >> 2;           // groupID 0..7
    const int lk = lane & 3;            // thread-in-group 0..3

    float acc[2][NT][4];
    #pragma unroll
    for (int mi = 0; mi < 2; ++mi)
        #pragma unroll
        for (int ni = 0; ni < NT; ++ni)
            #pragma unroll
            for (int q = 0; q < 4; ++q) acc[mi][ni][q] = 0.f;

    #pragma unroll
    for (int kk = 0; kk < 8; ++kk) {    // 8 k16 steps = K 128
        const int k0u = kk * 8;         // uint32 offset (16 bf16 = 8 uint32)
        uint32_t a[2][4];
        #pragma unroll
        for (int mi = 0; mi < 2; ++mi) {
            const int rb = warp_m * 32 + mi * 16;
            a[mi][0] = sA[(rb + lm)     * STU + k0u + lk];
            a[mi][1] = sA[(rb + 8 + lm) * STU + k0u + lk];
            a[mi][2] = sA[(rb + lm)     * STU + k0u + 4 + lk];
            a[mi][3] = sA[(rb + 8 + lm) * STU + k0u + 4 + lk];
        }
        uint32_t b[NT][2];
        #pragma unroll
        for (int ni = 0; ni < NT; ++ni) {
            const int nb = warp_n * (NT * 8) + ni * 8;
            b[ni][0] = sB[(nb + lm) * STU + k0u + lk];
            b[ni][1] = sB[(nb + lm) * STU + k0u + 4 + lk];
        }
        #pragma unroll
        for (int mi = 0; mi < 2; ++mi)
            #pragma unroll
            for (int ni = 0; ni < NT; ++ni) {
                asm volatile(
                    "mma.sync.aligned.m16n8k16.row.col.f32.bf16.bf16.f32 "
                    "{%0,%1,%2,%3}, {%4,%5,%6,%7}, {%8,%9}, {%0,%1,%2,%3};"
                    : "+f"(acc[mi][ni][0]), "+f"(acc[mi][ni][1]),
                      "+f"(acc[mi][ni][2]), "+f"(acc[mi][ni][3])
                    : "r"(a[mi][0]), "r"(a[mi][1]), "r"(a[mi][2]), "r"(a[mi][3]),
                      "r"(b[ni][0]), "r"(b[ni][1]));
            }
    }

    // epilogue: warp_n 0,1 -> Z (bf16) ; warp_n 2,3 -> Y (fp32)
    {
        const bool yhalf = (warp_n >= 2);
        const int cbase = warp_n * (NT * 8) - (yhalf ? D : 0);
        #pragma unroll
        for (int mi = 0; mi < 2; ++mi) {
            const int rl = row0 + warp_m * 32 + mi * 16 + lm;
            const int rh = rl + 8;
            #pragma unroll
            for (int ni = 0; ni < NT; ++ni) {
                const int oc = cbase + ni * 8 + lk * 2;
                if (yhalf) {
                    if (rl < NNODES)
                        *(float2*)&Y[rl * D + oc] = make_float2(acc[mi][ni][0], acc[mi][ni][1]);
                    if (rh < NNODES)
                        *(float2*)&Y[rh * D + oc] = make_float2(acc[mi][ni][2], acc[mi][ni][3]);
                } else {
                    if (rl < NNODES)
                        Zb[rl * (D / 2) + oc / 2] =
                            __float22bfloat162_rn(make_float2(acc[mi][ni][0], acc[mi][ni][1]));
                    if (rh < NNODES)
                        Zb[rh * (D / 2) + oc / 2] =
                            __float22bfloat162_rn(make_float2(acc[mi][ni][2], acc[mi][ni][3]));
                }
            }
        }
    }
}

// -------- gather + combine + relu (D=128): warp/node, 4-wide MLP ----------
__global__ __launch_bounds__(256)
void k_gather_combine128(const uint2* __restrict__ Zb, const float* __restrict__ Yb,
                         const float* __restrict__ bias, float* __restrict__ Hout) {
    const int w    = (blockIdx.x * blockDim.x + threadIdx.x) >> 5;
    const int lane = threadIdx.x & 31;
    if (w >= NNODES) return;
    int j = g_rowptr[w];
    const int e = g_rowptr[w + 1];
    float4 a0 = make_float4(0.f, 0.f, 0.f, 0.f);
    float4 a1 = make_float4(0.f, 0.f, 0.f, 0.f);
    float4 a2 = make_float4(0.f, 0.f, 0.f, 0.f);
    float4 a3 = make_float4(0.f, 0.f, 0.f, 0.f);
    for (; j + 3 < e; j += 4) {
        int s0 = g_csrc[j];
        int s1 = g_csrc[j + 1];
        int s2 = g_csrc[j + 2];
        int s3 = g_csrc[j + 3];
        uint2 u0 = Zb[s0 * 32 + lane];
        uint2 u1 = Zb[s1 * 32 + lane];
        uint2 u2 = Zb[s2 * 32 + lane];
        uint2 u3 = Zb[s3 * 32 + lane];
        float2 f;
        f = __bfloat1622float2(*(const __nv_bfloat162*)&u0.x); a0.x += f.x; a0.y += f.y;
        f = __bfloat1622float2(*(const __nv_bfloat162*)&u0.y); a0.z += f.x; a0.w += f.y;
        f = __bfloat1622float2(*(const __nv_bfloat162*)&u1.x); a1.x += f.x; a1.y += f.y;
        f = __bfloat1622float2(*(const __nv_bfloat162*)&u1.y); a1.z += f.x; a1.w += f.y;
        f = __bfloat1622float2(*(const __nv_bfloat162*)&u2.x); a2.x += f.x; a2.y += f.y;
        f = __bfloat1622float2(*(const __nv_bfloat162*)&u2.y); a2.z += f.x; a2.w += f.y;
        f = __bfloat1622float2(*(const __nv_bfloat162*)&u3.x); a3.x += f.x; a3.y += f.y;
        f = __bfloat1622float2(*(const __nv_bfloat162*)&u3.y); a3.z += f.x; a3.w += f.y;
    }
    for (; j < e; ++j) {
        int s0 = g_csrc[j];
        uint2 u0 = Zb[s0 * 32 + lane];
        float2 f;
        f = __bfloat1622float2(*(const __nv_bfloat162*)&u0.x); a0.x += f.x; a0.y += f.y;
        f = __bfloat1622float2(*(const __nv_bfloat162*)&u0.y); a0.z += f.x; a0.w += f.y;
    }
    a0.x += a1.x + a2.x + a3.x;
    a0.y += a1.y + a2.y + a3.y;
    a0.z += a1.z + a2.z + a3.z;
    a0.w += a1.w + a2.w + a3.w;
    float inv = g_dinv[w];
    float4 yv = ((const float4*)Yb)[w * 32 + lane];
    float4 bv = ((const float4*)bias)[lane];
    float4 o;
    o.x = fmaxf(a0.x * inv + yv.x + bv.x, 0.f);
    o.y = fmaxf(a0.y * inv + yv.y + bv.y, 0.f);
    o.z = fmaxf(a0.z * inv + yv.z + bv.z, 0.f);
    o.w = fmaxf(a0.w * inv + yv.w + bv.w, 0.f);
    ((float4*)Hout)[w * 32 + lane] = o;
}

// -------- gather + combine + log_softmax (D=64): 4-wide MLP --------
__global__ __launch_bounds__(256)
void k_gather_final64(const unsigned* __restrict__ Zb, const float* __restrict__ Yb,
                      const float* __restrict__ bias, float* __restrict__ out) {
    const int w    = (blockIdx.x * blockDim.x + threadIdx.x) >> 5;
    const int lane = threadIdx.x & 31;
    if (w >= NNODES) return;
    int j = g_rowptr[w];
    const int e = g_rowptr[w + 1];
    float2 a0 = make_float2(0.f, 0.f);
    float2 a1 = make_float2(0.f, 0.f);
    float2 a2 = make_float2(0.f, 0.f);
    float2 a3 = make_float2(0.f, 0.f);
    for (; j + 3 < e; j += 4) {
        int s0 = g_csrc[j];
        int s1 = g_csrc[j + 1];
        int s2 = g_csrc[j + 2];
        int s3 = g_csrc[j + 3];
        unsigned u0 = Zb[s0 * 32 + lane];
        unsigned u1 = Zb[s1 * 32 + lane];
        unsigned u2 = Zb[s2 * 32 + lane];
        unsigned u3 = Zb[s3 * 32 + lane];
        float2 f;
        f = __bfloat1622float2(*(const __nv_bfloat162*)&u0); a0.x += f.x; a0.y += f.y;
        f = __bfloat1622float2(*(const __nv_bfloat162*)&u1); a1.x += f.x; a1.y += f.y;
        f = __bfloat1622float2(*(const __nv_bfloat162*)&u2); a2.x += f.x; a2.y += f.y;
        f = __bfloat1622float2(*(const __nv_bfloat162*)&u3); a3.x += f.x; a3.y += f.y;
    }
    for (; j < e; ++j) {
        int s0 = g_csrc[j];
        unsigned u0 = Zb[s0 * 32 + lane];
        float2 f = __bfloat1622float2(*(const __nv_bfloat162*)&u0);
        a0.x += f.x; a0.y += f.y;
    }
    a0.x += a1.x + a2.x + a3.x;
    a0.y += a1.y + a2.y + a3.y;
    float inv = g_dinv[w];
    float2 yv = ((const float2*)Yb)[w * 32 + lane];
    float2 bv = ((const float2*)bias)[lane];
    float v0 = a0.x * inv + yv.x + bv.x;
    float v1 = a0.y * inv + yv.y + bv.y;
    float m = fmaxf(v0, v1);
    #pragma unroll
    for (int o = 16; o; o >>= 1) m = fmaxf(m, __shfl_xor_sync(0xffffffffu, m, o));
    float s = expf(v0 - m) + expf(v1 - m);
    #pragma unroll
    for (int o = 16; o; o >>= 1) s += __shfl_xor_sync(0xffffffffu, s, o);
    float lse = m + logf(s);
    out[w * 64 + lane * 2 + 0] = v0 - lse;
    out[w * 64 + lane * 2 + 1] = v1 - lse;
}

// ---------------- host launch ----------------
extern "C" void kernel_launch(void* const* d_in, const int* in_sizes, int n_in,
                              void* d_out, int out_size) {
    const float* x   = (const float*)d_in[0];
    const void*  ei  = d_in[1];
    const float* Wl0 = (const float*)d_in[2];
    const float* bl0 = (const float*)d_in[3];
    const float* Wr0 = (const float*)d_in[4];
    const float* Wl1 = (const float*)d_in[5];
    const float* bl1 = (const float*)d_in[6];
    const float* Wr1 = (const float*)d_in[7];
    const float* Wl2 = (const float*)d_in[8];
    const float* bl2 = (const float*)d_in[9];
    const float* Wr2 = (const float*)d_in[10];
    float* out = (float*)d_out;
    (void)in_sizes; (void)n_in; (void)out_size;

    void *p_deg, *p_fill, *p_zb, *p_y, *p_h;
    cudaGetSymbolAddress(&p_deg,  g_deg);
    cudaGetSymbolAddress(&p_fill, g_fill);
    cudaGetSymbolAddress(&p_zb,   g_zb);
    cudaGetSymbolAddress(&p_y,    g_y);
    cudaGetSymbolAddress(&p_h,    g_h);

    const int SM256 = (128 + 256) * 68 * 4;   // 104448
    const int SM128 = (128 + 128) * 68 * 4;   //  69632
    cudaFuncSetAttribute(k_gemm_mma<256>, cudaFuncAttributeMaxDynamicSharedMemorySize, SM256);
    cudaFuncSetAttribute(k_gemm_mma<128>, cudaFuncAttributeMaxDynamicSharedMemorySize, SM128);

    const int GT = (NNODES + 127) / 128;
    const int GW = (NNODES * 32 + 255) / 256;
    const int GE = (NEDGES + 255) / 256;

    // ---- prep (R10 structure: known-good) ----
    cudaMemsetAsync(p_deg,  0, NNODES * sizeof(int));
    cudaMemsetAsync(p_fill, 0, NNODES * sizeof(int));

    // layer-0 GEMM (edge-independent)
    k_gemm_mma<256><<<GT, 512, SM256>>>(x, Wl0, Wr0, (__nv_bfloat162*)p_zb, (float*)p_y);

    k_prep_edges<<<GE, 256>>>(ei);
    k_scan1<<<NBLK, SCAN_B>>>();
    k_scan3<<<(NNODES + SCAN_B - 1) / SCAN_B, SCAN_B>>>();
    k_fill<<<GE, 256>>>();

    // ---- layer 0 combine ----
    k_gather_combine128<<<GW, 256>>>((const uint2*)p_zb, (const float*)p_y, bl0, (float*)p_h);

    // ---- layer 1 ----
    k_gemm_mma<256><<<GT, 512, SM256>>>((const float*)p_h, Wl1, Wr1,
                                        (__nv_bfloat162*)p_zb, (float*)p_y);
    k_gather_combine128<<<GW, 256>>>((const uint2*)p_zb, (const float*)p_y, bl1, (float*)p_h);

    // ---- layer 2 + log_softmax ----
    k_gemm_mma<128><<<GT, 512, SM128>>>((const float*)p_h, Wl2, Wr2,
                                        (__nv_bfloat162*)p_zb, (float*)p_y);
    k_gather_final64<<<GW, 256>>>((const unsigned*)p_zb, (const float*)p_y, bl2, out);
}

// round 13
// speedup vs baseline: 1.2327x; 1.0218x over previous
#include <cuda_runtime.h>
#include <cuda_bf16.h>
#include <cstdint>

// ---------------- problem constants ----------------
#define NNODES 50000
#define NEDGES 800000
#define SCAN_B 256
#define NBLK   ((NNODES + SCAN_B - 1) / SCAN_B)   // 196

// ---------------- device scratch (no allocs allowed) ----------------
__device__ int   g_src[NEDGES];
__device__ int   g_dst[NEDGES];
__device__ int   g_deg[NNODES];
__device__ int   g_rowptr[NNODES + 1];
__device__ int   g_fill[NNODES];
__device__ int   g_csrc[NEDGES];
__device__ int   g_bsum[NBLK];
__device__ float g_dinv[NNODES];
__device__ uint2 g_zb[NNODES * 32];     // z bf16: 128 cols = 32 uint2
__device__ float g_y[NNODES * 128];
__device__ float g_h[NNODES * 128];

__device__ __forceinline__ uint32_t pack_bf2(float x, float y) {
    __nv_bfloat162 t = __float22bfloat162_rn(make_float2(x, y));
    return *(uint32_t*)&t;
}

// ---------------- edge decode + degree (dtype detected inline) ----------
__global__ void k_prep_edges(const void* __restrict__ ei_raw) {
    int i = blockIdx.x * blockDim.x + threadIdx.x;
    if (i >= NEDGES) return;
    const long long* e64 = (const long long*)ei_raw;
    bool is32 = false;
    #pragma unroll
    for (int q = 0; q < 4; ++q) {
        long long v = e64[q];
        if (v < 0 || v >= NNODES) is32 = true;
    }
    int d, s;
    if (is32) {
        const int* e = (const int*)ei_raw;
        d = e[i]; s = e[NEDGES + i];
    } else {
        d = (int)e64[i]; s = (int)e64[NEDGES + i];
    }
    g_dst[i] = d;
    g_src[i] = s;
    atomicAdd(&g_deg[d], 1);
}

// ---------------- CSR build ----------------
__global__ void k_scan1() {
    __shared__ int s[SCAN_B];
    int tid = threadIdx.x;
    int i = blockIdx.x * SCAN_B + tid;
    int v = (i < NNODES) ? g_deg[i] : 0;
    s[tid] = v;
    __syncthreads();
    #pragma unroll
    for (int off = 1; off < SCAN_B; off <<= 1) {
        int t = (tid >= off) ? s[tid - off] : 0;
        __syncthreads();
        s[tid] += t;
        __syncthreads();
    }
    if (i < NNODES) g_rowptr[i + 1] = s[tid];
    if (tid == SCAN_B - 1) g_bsum[blockIdx.x] = s[tid];
}

__global__ void k_scan3() {
    __shared__ int red[SCAN_B];
    int tid = threadIdx.x;
    int part = (tid < (int)blockIdx.x && tid < NBLK) ? g_bsum[tid] : 0;
    red[tid] = part;
    __syncthreads();
    #pragma unroll
    for (int off = SCAN_B / 2; off > 0; off >>= 1) {
        if (tid < off) red[tid] += red[tid + off];
        __syncthreads();
    }
    int offset = red[0];
    int i = blockIdx.x * SCAN_B + tid;
    if (i == 0) g_rowptr[0] = 0;
    if (i < NNODES) {
        g_rowptr[i + 1] += offset;
        g_dinv[i] = 1.0f / fmaxf((float)g_deg[i], 1.0f);
    }
}
__global__ void k_fill() {
    int i = blockIdx.x * blockDim.x + threadIdx.x;
    if (i >= NEDGES) return;
    int d = g_dst[i];
    int pos = g_rowptr[d] + atomicAdd(&g_fill[d], 1);
    g_csrc[pos] = g_src[i];
}

// ---------------- mma.sync bf16 m16n8k16 dual GEMM ----------------
template <int NC>
__global__ __launch_bounds__(512, 1)
void k_gemm_mma(const float* __restrict__ H,
                const float* __restrict__ Wl, const float* __restrict__ Wr,
                __nv_bfloat162* __restrict__ Zb, float* __restrict__ Y) {
    constexpr int D   = NC / 2;
    constexpr int NT  = NC / 32;
    constexpr int STU = 68;

    extern __shared__ uint32_t smem[];
    uint32_t* sA = smem;                // 128 x STU
    uint32_t* sB = smem + 128 * STU;    // NC x STU

    const int tid  = threadIdx.x;
    const int wid  = tid >> 5;
    const int lane = tid & 31;
    const int row0 = blockIdx.x * 128;

    {
        const float4* h4 = (const float4*)H;
        #pragma unroll
        for (int i = tid; i < 128 * 32; i += 512) {
            int r = i >> 5, c = i & 31;
            int gr = row0 + r;
            float4 v = make_float4(0.f, 0.f, 0.f, 0.f);
            if (gr < NNODES) v = h4[gr * 32 + c];
            uint2 p = make_uint2(pack_bf2(v.x, v.y), pack_bf2(v.z, v.w));
            *(uint2*)&sA[r * STU + c * 2] = p;
        }
    }
    {
        #pragma unroll
        for (int i = tid; i < NC * 32; i += 512) {
            int n = i >> 5, c = i & 31;
            const float4* wsrc = (const float4*)((n < D) ? (Wl + n * 128)
                                                         : (Wr + (n - D) * 128));
            float4 v = wsrc[c];
            uint2 p = make_uint2(pack_bf2(v.x, v.y), pack_bf2(v.z, v.w));
            *(uint2*)&sB[n * STU + c * 2] = p;
        }
    }
    __syncthreads();

    const int warp_m = wid & 3;
    const int warp_n = wid >> 2;
    const int lm = lane >> 2;
    const int lk = lane & 3;

    float acc[2][NT][4];
    #pragma unroll
    for (int mi = 0; mi < 2; ++mi)
        #pragma unroll
        for (int ni = 0; ni < NT; ++ni)
            #pragma unroll
            for (int q = 0; q < 4; ++q) acc[mi][ni][q] = 0.f;

    #pragma unroll
    for (int kk = 0; kk < 8; ++kk) {
        const int k0u = kk * 8;
        uint32_t a[2][4];
        #pragma unroll
        for (int mi = 0; mi < 2; ++mi) {
            const int rb = warp_m * 32 + mi * 16;
            a[mi][0] = sA[(rb + lm)     * STU + k0u + lk];
            a[mi][1] = sA[(rb + 8 + lm) * STU + k0u + lk];
            a[mi][2] = sA[(rb + lm)     * STU + k0u + 4 + lk];
            a[mi][3] = sA[(rb + 8 + lm) * STU + k0u + 4 + lk];
        }
        uint32_t b[NT][2];
        #pragma unroll
        for (int ni = 0; ni < NT; ++ni) {
            const int nb = warp_n * (NT * 8) + ni * 8;
            b[ni][0] = sB[(nb + lm) * STU + k0u + lk];
            b[ni][1] = sB[(nb + lm) * STU + k0u + 4 + lk];
        }
        #pragma unroll
        for (int mi = 0; mi < 2; ++mi)
            #pragma unroll
            for (int ni = 0; ni < NT; ++ni) {
                asm volatile(
                    "mma.sync.aligned.m16n8k16.row.col.f32.bf16.bf16.f32 "
                    "{%0,%1,%2,%3}, {%4,%5,%6,%7}, {%8,%9}, {%0,%1,%2,%3};"
                    : "+f"(acc[mi][ni][0]), "+f"(acc[mi][ni][1]),
                      "+f"(acc[mi][ni][2]), "+f"(acc[mi][ni][3])
                    : "r"(a[mi][0]), "r"(a[mi][1]), "r"(a[mi][2]), "r"(a[mi][3]),
                      "r"(b[ni][0]), "r"(b[ni][1]));
            }
    }

    {
        const bool yhalf = (warp_n >= 2);
        const int cbase = warp_n * (NT * 8) - (yhalf ? D : 0);
        #pragma unroll
        for (int mi = 0; mi < 2; ++mi) {
            const int rl = row0 + warp_m * 32 + mi * 16 + lm;
            const int rh = rl + 8;
            #pragma unroll
            for (int ni = 0; ni < NT; ++ni) {
                const int oc = cbase + ni * 8 + lk * 2;
                if (yhalf) {
                    if (rl < NNODES)
                        *(float2*)&Y[rl * D + oc] = make_float2(acc[mi][ni][0], acc[mi][ni][1]);
                    if (rh < NNODES)
                        *(float2*)&Y[rh * D + oc] = make_float2(acc[mi][ni][2], acc[mi][ni][3]);
                } else {
                    if (rl < NNODES)
                        Zb[rl * (D / 2) + oc / 2] =
                            __float22bfloat162_rn(make_float2(acc[mi][ni][0], acc[mi][ni][1]));
                    if (rh < NNODES)
                        Zb[rh * (D / 2) + oc / 2] =
                            __float22bfloat162_rn(make_float2(acc[mi][ni][2], acc[mi][ni][3]));
                }
            }
        }
    }
}

// -------- gather + combine + relu (D=128): warp/node, 4-wide MLP ----------
__global__ __launch_bounds__(256)
void k_gather_combine128(const uint2* __restrict__ Zb, const float* __restrict__ Yb,
                         const float* __restrict__ bias, float* __restrict__ Hout) {
    const int w    = (blockIdx.x * blockDim.x + threadIdx.x) >> 5;
    const int lane = threadIdx.x & 31;
    if (w >= NNODES) return;
    int j = g_rowptr[w];
    const int e = g_rowptr[w + 1];
    float4 a0 = make_float4(0.f, 0.f, 0.f, 0.f);
    float4 a1 = make_float4(0.f, 0.f, 0.f, 0.f);
    float4 a2 = make_float4(0.f, 0.f, 0.f, 0.f);
    float4 a3 = make_float4(0.f, 0.f, 0.f, 0.f);
    for (; j + 3 < e; j += 4) {
        int s0 = g_csrc[j];
        int s1 = g_csrc[j + 1];
        int s2 = g_csrc[j + 2];
        int s3 = g_csrc[j + 3];
        uint2 u0 = Zb[s0 * 32 + lane];
        uint2 u1 = Zb[s1 * 32 + lane];
        uint2 u2 = Zb[s2 * 32 + lane];
        uint2 u3 = Zb[s3 * 32 + lane];
        float2 f;
        f = __bfloat1622float2(*(const __nv_bfloat162*)&u0.x); a0.x += f.x; a0.y += f.y;
        f = __bfloat1622float2(*(const __nv_bfloat162*)&u0.y); a0.z += f.x; a0.w += f.y;
        f = __bfloat1622float2(*(const __nv_bfloat162*)&u1.x); a1.x += f.x; a1.y += f.y;
        f = __bfloat1622float2(*(const __nv_bfloat162*)&u1.y); a1.z += f.x; a1.w += f.y;
        f = __bfloat1622float2(*(const __nv_bfloat162*)&u2.x); a2.x += f.x; a2.y += f.y;
        f = __bfloat1622float2(*(const __nv_bfloat162*)&u2.y); a2.z += f.x; a2.w += f.y;
        f = __bfloat1622float2(*(const __nv_bfloat162*)&u3.x); a3.x += f.x; a3.y += f.y;
        f = __bfloat1622float2(*(const __nv_bfloat162*)&u3.y); a3.z += f.x; a3.w += f.y;
    }
    for (; j < e; ++j) {
        int s0 = g_csrc[j];
        uint2 u0 = Zb[s0 * 32 + lane];
        float2 f;
        f = __bfloat1622float2(*(const __nv_bfloat162*)&u0.x); a0.x += f.x; a0.y += f.y;
        f = __bfloat1622float2(*(const __nv_bfloat162*)&u0.y); a0.z += f.x; a0.w += f.y;
    }
    a0.x += a1.x + a2.x + a3.x;
    a0.y += a1.y + a2.y + a3.y;
    a0.z += a1.z + a2.z + a3.z;
    a0.w += a1.w + a2.w + a3.w;
    float inv = g_dinv[w];
    float4 yv = ((const float4*)Yb)[w * 32 + lane];
    float4 bv = ((const float4*)bias)[lane];
    float4 o;
    o.x = fmaxf(a0.x * inv + yv.x + bv.x, 0.f);
    o.y = fmaxf(a0.y * inv + yv.y + bv.y, 0.f);
    o.z = fmaxf(a0.z * inv + yv.z + bv.z, 0.f);
    o.w = fmaxf(a0.w * inv + yv.w + bv.w, 0.f);
    ((float4*)Hout)[w * 32 + lane] = o;
}

// -------- gather + combine + log_softmax (D=64): 4-wide MLP --------
__global__ __launch_bounds__(256)
void k_gather_final64(const unsigned* __restrict__ Zb, const float* __restrict__ Yb,
                      const float* __restrict__ bias, float* __restrict__ out) {
    const int w    = (blockIdx.x * blockDim.x + threadIdx.x) >> 5;
    const int lane = threadIdx.x & 31;
    if (w >= NNODES) return;
    int j = g_rowptr[w];
    const int e = g_rowptr[w + 1];
    float2 a0 = make_float2(0.f, 0.f);
    float2 a1 = make_float2(0.f, 0.f);
    float2 a2 = make_float2(0.f, 0.f);
    float2 a3 = make_float2(0.f, 0.f);
    for (; j + 3 < e; j += 4) {
        int s0 = g_csrc[j];
        int s1 = g_csrc[j + 1];
        int s2 = g_csrc[j + 2];
        int s3 = g_csrc[j + 3];
        unsigned u0 = Zb[s0 * 32 + lane];
        unsigned u1 = Zb[s1 * 32 + lane];
        unsigned u2 = Zb[s2 * 32 + lane];
        unsigned u3 = Zb[s3 * 32 + lane];
        float2 f;
        f = __bfloat1622float2(*(const __nv_bfloat162*)&u0); a0.x += f.x; a0.y += f.y;
        f = __bfloat1622float2(*(const __nv_bfloat162*)&u1); a1.x += f.x; a1.y += f.y;
        f = __bfloat1622float2(*(const __nv_bfloat162*)&u2); a2.x += f.x; a2.y += f.y;
        f = __bfloat1622float2(*(const __nv_bfloat162*)&u3); a3.x += f.x; a3.y += f.y;
    }
    for (; j < e; ++j) {
        int s0 = g_csrc[j];
        unsigned u0 = Zb[s0 * 32 + lane];
        float2 f = __bfloat1622float2(*(const __nv_bfloat162*)&u0);
        a0.x += f.x; a0.y += f.y;
    }
    a0.x += a1.x + a2.x + a3.x;
    a0.y += a1.y + a2.y + a3.y;
    float inv = g_dinv[w];
    float2 yv = ((const float2*)Yb)[w * 32 + lane];
    float2 bv = ((const float2*)bias)[lane];
    float v0 = a0.x * inv + yv.x + bv.x;
    float v1 = a0.y * inv + yv.y + bv.y;
    float m = fmaxf(v0, v1);
    #pragma unroll
    for (int o = 16; o; o >>= 1) m = fmaxf(m, __shfl_xor_sync(0xffffffffu, m, o));
    float s = expf(v0 - m) + expf(v1 - m);
    #pragma unroll
    for (int o = 16; o; o >>= 1) s += __shfl_xor_sync(0xffffffffu, s, o);
    float lse = m + logf(s);
    out[w * 64 + lane * 2 + 0] = v0 - lse;
    out[w * 64 + lane * 2 + 1] = v1 - lse;
}

// ---------------- host launch ----------------
extern "C" void kernel_launch(void* const* d_in, const int* in_sizes, int n_in,
                              void* d_out, int out_size) {
    const float* x   = (const float*)d_in[0];
    const void*  ei  = d_in[1];
    const float* Wl0 = (const float*)d_in[2];
    const float* bl0 = (const float*)d_in[3];
    const float* Wr0 = (const float*)d_in[4];
    const float* Wl1 = (const float*)d_in[5];
    const float* bl1 = (const float*)d_in[6];
    const float* Wr1 = (const float*)d_in[7];
    const float* Wl2 = (const float*)d_in[8];
    const float* bl2 = (const float*)d_in[9];
    const float* Wr2 = (const float*)d_in[10];
    float* out = (float*)d_out;
    (void)in_sizes; (void)n_in; (void)out_size;

    void *p_deg, *p_fill, *p_zb, *p_y, *p_h;
    cudaGetSymbolAddress(&p_deg,  g_deg);
    cudaGetSymbolAddress(&p_fill, g_fill);
    cudaGetSymbolAddress(&p_zb,   g_zb);
    cudaGetSymbolAddress(&p_y,    g_y);
    cudaGetSymbolAddress(&p_h,    g_h);

    // lazily-created side stream + fork/join events (host resources only)
    static cudaStream_t s2 = nullptr;
    static cudaEvent_t  ev_fork = nullptr, ev_join = nullptr;
    if (!s2) {
        cudaStreamCreateWithFlags(&s2, cudaStreamNonBlocking);
        cudaEventCreateWithFlags(&ev_fork, cudaEventDisableTiming);
        cudaEventCreateWithFlags(&ev_join, cudaEventDisableTiming);
    }

    const int SM256 = (128 + 256) * 68 * 4;   // 104448
    const int SM128 = (128 + 128) * 68 * 4;   //  69632
    cudaFuncSetAttribute(k_gemm_mma<256>, cudaFuncAttributeMaxDynamicSharedMemorySize, SM256);
    cudaFuncSetAttribute(k_gemm_mma<128>, cudaFuncAttributeMaxDynamicSharedMemorySize, SM128);

    const int GT = (NNODES + 127) / 128;
    const int GW = (NNODES * 32 + 255) / 256;
    const int GE = (NEDGES + 255) / 256;

    // ---- fork: prep chain on s2 || layer-0 GEMM on main stream ----
    cudaEventRecord(ev_fork, 0);
    cudaStreamWaitEvent(s2, ev_fork, 0);

    cudaMemsetAsync(p_deg,  0, NNODES * sizeof(int), s2);
    cudaMemsetAsync(p_fill, 0, NNODES * sizeof(int), s2);
    k_prep_edges<<<GE, 256, 0, s2>>>(ei);
    k_scan1<<<NBLK, SCAN_B, 0, s2>>>();
    k_scan3<<<(NNODES + SCAN_B - 1) / SCAN_B, SCAN_B, 0, s2>>>();
    k_fill<<<GE, 256, 0, s2>>>();
    cudaEventRecord(ev_join, s2);

    k_gemm_mma<256><<<GT, 512, SM256>>>(x, Wl0, Wr0, (__nv_bfloat162*)p_zb, (float*)p_y);

    // ---- join: gather needs both CSR and z/y ----
    cudaStreamWaitEvent(0, ev_join, 0);

    // ---- layer 0 combine ----
    k_gather_combine128<<<GW, 256>>>((const uint2*)p_zb, (const float*)p_y, bl0, (float*)p_h);

    // ---- layer 1 ----
    k_gemm_mma<256><<<GT, 512, SM256>>>((const float*)p_h, Wl1, Wr1,
                                        (__nv_bfloat162*)p_zb, (float*)p_y);
    k_gather_combine128<<<GW, 256>>>((const uint2*)p_zb, (const float*)p_y, bl1, (float*)p_h);

    // ---- layer 2 + log_softmax ----
    k_gemm_mma<128><<<GT, 512, SM128>>>((const float*)p_h, Wl2, Wr2,
                                        (__nv_bfloat162*)p_zb, (float*)p_y);
    k_gather_final64<<<GW, 256>>>((const unsigned*)p_zb, (const float*)p_y, bl2, out);
}

// round 14
// speedup vs baseline: 1.2704x; 1.0306x over previous
#include <cuda_runtime.h>
#include <cuda_bf16.h>
#include <cstdint>

// ---------------- problem constants ----------------
#define NNODES 50000
#define NEDGES 800000
#define SCAN_B 256
#define NBLK   ((NNODES + SCAN_B - 1) / SCAN_B)   // 196

// ---------------- device scratch (no allocs allowed) ----------------
__device__ int   g_deg[NNODES];
__device__ int   g_rowptr[NNODES + 1];
__device__ int   g_fill[NNODES];        // seeded to row start in scan3
__device__ int   g_csrc[NEDGES];
__device__ int   g_bsum[NBLK];
__device__ float g_dinv[NNODES];
__device__ uint2 g_zb[NNODES * 32];     // z bf16: 128 cols = 32 uint2
__device__ float g_y[NNODES * 128];
__device__ float g_h[NNODES * 128];

__device__ __forceinline__ uint32_t pack_bf2(float x, float y) {
    __nv_bfloat162 t = __float22bfloat162_rn(make_float2(x, y));
    return *(uint32_t*)&t;
}
__device__ __forceinline__ uint32_t smem_addr32(const void* p) {
    uint32_t a;
    asm("{ .reg .u64 t; cvta.to.shared.u64 t, %1; cvt.u32.u64 %0, t; }" : "=r"(a) : "l"(p));
    return a;
}
__device__ __forceinline__ void ldm_x4(uint32_t& r0, uint32_t& r1, uint32_t& r2, uint32_t& r3,
                                       uint32_t addr) {
    asm volatile("ldmatrix.sync.aligned.m8n8.x4.shared.b16 {%0,%1,%2,%3}, [%4];"
                 : "=r"(r0), "=r"(r1), "=r"(r2), "=r"(r3) : "r"(addr));
}
__device__ __forceinline__ bool edges_are_int32(const long long* e64) {
    bool is32 = false;
    #pragma unroll
    for (int q = 0; q < 4; ++q) {        // broadcast loads; uniform branch
        long long v = e64[q];
        if (v < 0 || v >= NNODES) is32 = true;
    }
    return is32;
}

// ---------------- degree (reads dst half of edge_index only) ----------
__global__ void k_deg(const void* __restrict__ ei_raw) {
    int i = blockIdx.x * blockDim.x + threadIdx.x;
    if (i >= NEDGES) return;
    const long long* e64 = (const long long*)ei_raw;
    int d;
    if (edges_are_int32(e64)) d = ((const int*)ei_raw)[i];
    else                      d = (int)e64[i];
    atomicAdd(&g_deg[d], 1);
}

// ---------------- CSR scans ----------------
__global__ void k_scan1() {
    __shared__ int s[SCAN_B];
    int tid = threadIdx.x;
    int i = blockIdx.x * SCAN_B + tid;
    int v = (i < NNODES) ? g_deg[i] : 0;
    s[tid] = v;
    __syncthreads();
    #pragma unroll
    for (int off = 1; off < SCAN_B; off <<= 1) {
        int t = (tid >= off) ? s[tid - off] : 0;
        __syncthreads();
        s[tid] += t;
        __syncthreads();
    }
    if (i < NNODES) g_rowptr[i + 1] = s[tid];
    if (tid == SCAN_B - 1) g_bsum[blockIdx.x] = s[tid];
}

__global__ void k_scan3() {
    __shared__ int red[SCAN_B];
    int tid = threadIdx.x;
    int part = (tid < (int)blockIdx.x && tid < NBLK) ? g_bsum[tid] : 0;
    red[tid] = part;
    __syncthreads();
    #pragma unroll
    for (int off = SCAN_B / 2; off > 0; off >>= 1) {
        if (tid < off) red[tid] += red[tid + off];
        __syncthreads();
    }
    int offset = red[0];
    int i = blockIdx.x * SCAN_B + tid;
    if (i == 0) g_rowptr[0] = 0;
    if (i < NNODES) {
        int deg = g_deg[i];
        int end = g_rowptr[i + 1] + offset;
        g_rowptr[i + 1] = end;
        g_fill[i] = end - deg;                 // row start = fill cursor seed
        g_dinv[i] = 1.0f / fmaxf((float)deg, 1.0f);
    }
}

// ---------------- CSR fill: re-reads edge_index, cursor atomics ----------
__global__ void k_fill(const void* __restrict__ ei_raw) {
    int i = blockIdx.x * blockDim.x + threadIdx.x;
    if (i >= NEDGES) return;
    const long long* e64 = (const long long*)ei_raw;
    int d, s;
    if (edges_are_int32(e64)) {
        const int* e = (const int*)ei_raw;
        d = e[i]; s = e[NEDGES + i];
    } else {
        d = (int)e64[i]; s = (int)e64[NEDGES + i];
    }
    int pos = atomicAdd(&g_fill[d], 1);
    g_csrc[pos] = s;
}

// ---------------- mma.sync bf16 m16n8k16 dual GEMM (ldmatrix loads) ------
template <int NC>
__global__ __launch_bounds__(512, 1)
void k_gemm_mma(const float* __restrict__ H,
                const float* __restrict__ Wl, const float* __restrict__ Wr,
                __nv_bfloat162* __restrict__ Zb, float* __restrict__ Y) {
    constexpr int D   = NC / 2;
    constexpr int NT  = NC / 32;        // n-frags per warp (8 / 4)
    constexpr int NP  = NT / 2;         // ldmatrix pairs   (4 / 2)
    constexpr int STU = 68;             // row stride in uint32

    extern __shared__ uint32_t smem[];
    uint32_t* sA = smem;                // 128 x STU
    uint32_t* sB = smem + 128 * STU;    // NC x STU

    const int tid  = threadIdx.x;
    const int wid  = tid >> 5;
    const int lane = tid & 31;
    const int row0 = blockIdx.x * 128;

    {
        const float4* h4 = (const float4*)H;
        #pragma unroll
        for (int i = tid; i < 128 * 32; i += 512) {
            int r = i >> 5, c = i & 31;
            int gr = row0 + r;
            float4 v = make_float4(0.f, 0.f, 0.f, 0.f);
            if (gr < NNODES) v = h4[gr * 32 + c];
            uint2 p = make_uint2(pack_bf2(v.x, v.y), pack_bf2(v.z, v.w));
            *(uint2*)&sA[r * STU + c * 2] = p;
        }
    }
    {
        #pragma unroll
        for (int i = tid; i < NC * 32; i += 512) {
            int n = i >> 5, c = i & 31;
            const float4* wsrc = (const float4*)((n < D) ? (Wl + n * 128)
                                                         : (Wr + (n - D) * 128));
            float4 v = wsrc[c];
            uint2 p = make_uint2(pack_bf2(v.x, v.y), pack_bf2(v.z, v.w));
            *(uint2*)&sB[n * STU + c * 2] = p;
        }
    }
    __syncthreads();

    const int warp_m = wid & 3;
    const int warp_n = wid >> 2;
    const int lm = lane >> 2;
    const int lk = lane & 3;

    // ldmatrix per-lane address components:
    // matrices: lanes 0-7 -> {row-lo, k-lo}, 8-15 -> {row-hi, k-lo},
    //           16-23 -> {row-lo, k-hi}, 24-31 -> {row-hi, k-hi}
    const int lrow = (lane & 7) + ((lane >> 3) & 1) * 8;   // row within 16
    const int lkof = (lane >> 4) * 4;                      // 0 or 4 uint32
    const uint32_t sa32 = smem_addr32(sA);
    const uint32_t sb32 = smem_addr32(sB);

    float acc[2][NT][4];
    #pragma unroll
    for (int mi = 0; mi < 2; ++mi)
        #pragma unroll
        for (int ni = 0; ni < NT; ++ni)
            #pragma unroll
            for (int q = 0; q < 4; ++q) acc[mi][ni][q] = 0.f;

    #pragma unroll
    for (int kk = 0; kk < 8; ++kk) {
        const int k0u = kk * 8;
        uint32_t a[2][4];
        #pragma unroll
        for (int mi = 0; mi < 2; ++mi) {
            const int rb = warp_m * 32 + mi * 16;
            uint32_t ad = sa32 + (uint32_t)(((rb + lrow) * STU + k0u + lkof) * 4);
            ldm_x4(a[mi][0], a[mi][1], a[mi][2], a[mi][3], ad);
        }
        uint32_t b[NT][2];
        #pragma unroll
        for (int p = 0; p < NP; ++p) {
            const int nb = warp_n * (NT * 8) + p * 16;
            uint32_t bd = sb32 + (uint32_t)(((nb + lrow) * STU + k0u + lkof) * 4);
            // r0 = b[2p][0] (n-lo,k-lo), r1 = b[2p+1][0] (n-hi,k-lo),
            // r2 = b[2p][1] (n-lo,k-hi), r3 = b[2p+1][1]
            ldm_x4(b[2 * p][0], b[2 * p + 1][0], b[2 * p][1], b[2 * p + 1][1], bd);
        }
        #pragma unroll
        for (int mi = 0; mi < 2; ++mi)
            #pragma unroll
            for (int ni = 0; ni < NT; ++ni) {
                asm volatile(
                    "mma.sync.aligned.m16n8k16.row.col.f32.bf16.bf16.f32 "
                    "{%0,%1,%2,%3}, {%4,%5,%6,%7}, {%8,%9}, {%0,%1,%2,%3};"
                    : "+f"(acc[mi][ni][0]), "+f"(acc[mi][ni][1]),
                      "+f"(acc[mi][ni][2]), "+f"(acc[mi][ni][3])
                    : "r"(a[mi][0]), "r"(a[mi][1]), "r"(a[mi][2]), "r"(a[mi][3]),
                      "r"(b[ni][0]), "r"(b[ni][1]));
            }
    }

    {
        const bool yhalf = (warp_n >= 2);
        const int cbase = warp_n * (NT * 8) - (yhalf ? D : 0);
        #pragma unroll
        for (int mi = 0; mi < 2; ++mi) {
            const int rl = row0 + warp_m * 32 + mi * 16 + lm;
            const int rh = rl + 8;
            #pragma unroll
            for (int ni = 0; ni < NT; ++ni) {
                const int oc = cbase + ni * 8 + lk * 2;
                if (yhalf) {
                    if (rl < NNODES)
                        *(float2*)&Y[rl * D + oc] = make_float2(acc[mi][ni][0], acc[mi][ni][1]);
                    if (rh < NNODES)
                        *(float2*)&Y[rh * D + oc] = make_float2(acc[mi][ni][2], acc[mi][ni][3]);
                } else {
                    if (rl < NNODES)
                        Zb[rl * (D / 2) + oc / 2] =
                            __float22bfloat162_rn(make_float2(acc[mi][ni][0], acc[mi][ni][1]));
                    if (rh < NNODES)
                        Zb[rh * (D / 2) + oc / 2] =
                            __float22bfloat162_rn(make_float2(acc[mi][ni][2], acc[mi][ni][3]));
                }
            }
        }
    }
}

// -------- gather + combine + relu (D=128): warp/node, 4-wide MLP ----------
__global__ __launch_bounds__(256)
void k_gather_combine128(const uint2* __restrict__ Zb, const float* __restrict__ Yb,
                         const float* __restrict__ bias, float* __restrict__ Hout) {
    const int w    = (blockIdx.x * blockDim.x + threadIdx.x) >> 5;
    const int lane = threadIdx.x & 31;
    if (w >= NNODES) return;
    int j = g_rowptr[w];
    const int e = g_rowptr[w + 1];
    float4 a0 = make_float4(0.f, 0.f, 0.f, 0.f);
    float4 a1 = make_float4(0.f, 0.f, 0.f, 0.f);
    float4 a2 = make_float4(0.f, 0.f, 0.f, 0.f);
    float4 a3 = make_float4(0.f, 0.f, 0.f, 0.f);
    for (; j + 3 < e; j += 4) {
        int s0 = g_csrc[j];
        int s1 = g_csrc[j + 1];
        int s2 = g_csrc[j + 2];
        int s3 = g_csrc[j + 3];
        uint2 u0 = Zb[s0 * 32 + lane];
        uint2 u1 = Zb[s1 * 32 + lane];
        uint2 u2 = Zb[s2 * 32 + lane];
        uint2 u3 = Zb[s3 * 32 + lane];
        float2 f;
        f = __bfloat1622float2(*(const __nv_bfloat162*)&u0.x); a0.x += f.x; a0.y += f.y;
        f = __bfloat1622float2(*(const __nv_bfloat162*)&u0.y); a0.z += f.x; a0.w += f.y;
        f = __bfloat1622float2(*(const __nv_bfloat162*)&u1.x); a1.x += f.x; a1.y += f.y;
        f = __bfloat1622float2(*(const __nv_bfloat162*)&u1.y); a1.z += f.x; a1.w += f.y;
        f = __bfloat1622float2(*(const __nv_bfloat162*)&u2.x); a2.x += f.x; a2.y += f.y;
        f = __bfloat1622float2(*(const __nv_bfloat162*)&u2.y); a2.z += f.x; a2.w += f.y;
        f = __bfloat1622float2(*(const __nv_bfloat162*)&u3.x); a3.x += f.x; a3.y += f.y;
        f = __bfloat1622float2(*(const __nv_bfloat162*)&u3.y); a3.z += f.x; a3.w += f.y;
    }
    for (; j < e; ++j) {
        int s0 = g_csrc[j];
        uint2 u0 = Zb[s0 * 32 + lane];
        float2 f;
        f = __bfloat1622float2(*(const __nv_bfloat162*)&u0.x); a0.x += f.x; a0.y += f.y;
        f = __bfloat1622float2(*(const __nv_bfloat162*)&u0.y); a0.z += f.x; a0.w += f.y;
    }
    a0.x += a1.x + a2.x + a3.x;
    a0.y += a1.y + a2.y + a3.y;
    a0.z += a1.z + a2.z + a3.z;
    a0.w += a1.w + a2.w + a3.w;
    float inv = g_dinv[w];
    float4 yv = ((const float4*)Yb)[w * 32 + lane];
    float4 bv = ((const float4*)bias)[lane];
    float4 o;
    o.x = fmaxf(a0.x * inv + yv.x + bv.x, 0.f);
    o.y = fmaxf(a0.y * inv + yv.y + bv.y, 0.f);
    o.z = fmaxf(a0.z * inv + yv.z + bv.z, 0.f);
    o.w = fmaxf(a0.w * inv + yv.w + bv.w, 0.f);
    ((float4*)Hout)[w * 32 + lane] = o;
}

// -------- gather + combine + log_softmax (D=64): 4-wide MLP --------
__global__ __launch_bounds__(256)
void k_gather_final64(const unsigned* __restrict__ Zb, const float* __restrict__ Yb,
                      const float* __restrict__ bias, float* __restrict__ out) {
    const int w    = (blockIdx.x * blockDim.x + threadIdx.x) >> 5;
    const int lane = threadIdx.x & 31;
    if (w >= NNODES) return;
    int j = g_rowptr[w];
    const int e = g_rowptr[w + 1];
    float2 a0 = make_float2(0.f, 0.f);
    float2 a1 = make_float2(0.f, 0.f);
    float2 a2 = make_float2(0.f, 0.f);
    float2 a3 = make_float2(0.f, 0.f);
    for (; j + 3 < e; j += 4) {
        int s0 = g_csrc[j];
        int s1 = g_csrc[j + 1];
        int s2 = g_csrc[j + 2];
        int s3 = g_csrc[j + 3];
        unsigned u0 = Zb[s0 * 32 + lane];
        unsigned u1 = Zb[s1 * 32 + lane];
        unsigned u2 = Zb[s2 * 32 + lane];
        unsigned u3 = Zb[s3 * 32 + lane];
        float2 f;
        f = __bfloat1622float2(*(const __nv_bfloat162*)&u0); a0.x += f.x; a0.y += f.y;
        f = __bfloat1622float2(*(const __nv_bfloat162*)&u1); a1.x += f.x; a1.y += f.y;
        f = __bfloat1622float2(*(const __nv_bfloat162*)&u2); a2.x += f.x; a2.y += f.y;
        f = __bfloat1622float2(*(const __nv_bfloat162*)&u3); a3.x += f.x; a3.y += f.y;
    }
    for (; j < e; ++j) {
        int s0 = g_csrc[j];
        unsigned u0 = Zb[s0 * 32 + lane];
        float2 f = __bfloat1622float2(*(const __nv_bfloat162*)&u0);
        a0.x += f.x; a0.y += f.y;
    }
    a0.x += a1.x + a2.x + a3.x;
    a0.y += a1.y + a2.y + a3.y;
    float inv = g_dinv[w];
    float2 yv = ((const float2*)Yb)[w * 32 + lane];
    float2 bv = ((const float2*)bias)[lane];
    float v0 = a0.x * inv + yv.x + bv.x;
    float v1 = a0.y * inv + yv.y + bv.y;
    float m = fmaxf(v0, v1);
    #pragma unroll
    for (int o = 16; o; o >>= 1) m = fmaxf(m, __shfl_xor_sync(0xffffffffu, m, o));
    float s = expf(v0 - m) + expf(v1 - m);
    #pragma unroll
    for (int o = 16; o; o >>= 1) s += __shfl_xor_sync(0xffffffffu, s, o);
    float lse = m + logf(s);
    out[w * 64 + lane * 2 + 0] = v0 - lse;
    out[w * 64 + lane * 2 + 1] = v1 - lse;
}

// ---------------- host launch ----------------
extern "C" void kernel_launch(void* const* d_in, const int* in_sizes, int n_in,
                              void* d_out, int out_size) {
    const float* x   = (const float*)d_in[0];
    const void*  ei  = d_in[1];
    const float* Wl0 = (const float*)d_in[2];
    const float* bl0 = (const float*)d_in[3];
    const float* Wr0 = (const float*)d_in[4];
    const float* Wl1 = (const float*)d_in[5];
    const float* bl1 = (const float*)d_in[6];
    const float* Wr1 = (const float*)d_in[7];
    const float* Wl2 = (const float*)d_in[8];
    const float* bl2 = (const float*)d_in[9];
    const float* Wr2 = (const float*)d_in[10];
    float* out = (float*)d_out;
    (void)in_sizes; (void)n_in; (void)out_size;

    void *p_deg, *p_zb, *p_y, *p_h;
    cudaGetSymbolAddress(&p_deg, g_deg);
    cudaGetSymbolAddress(&p_zb,  g_zb);
    cudaGetSymbolAddress(&p_y,   g_y);
    cudaGetSymbolAddress(&p_h,   g_h);

    static cudaStream_t s2 = nullptr;
    static cudaEvent_t  ev_fork = nullptr, ev_join = nullptr;
    if (!s2) {
        cudaStreamCreateWithFlags(&s2, cudaStreamNonBlocking);
        cudaEventCreateWithFlags(&ev_fork, cudaEventDisableTiming);
        cudaEventCreateWithFlags(&ev_join, cudaEventDisableTiming);
    }

    const int SM256 = (128 + 256) * 68 * 4;   // 104448
    const int SM128 = (128 + 128) * 68 * 4;   //  69632
    cudaFuncSetAttribute(k_gemm_mma<256>, cudaFuncAttributeMaxDynamicSharedMemorySize, SM256);
    cudaFuncSetAttribute(k_gemm_mma<128>, cudaFuncAttributeMaxDynamicSharedMemorySize, SM128);

    const int GT = (NNODES + 127) / 128;
    const int GW = (NNODES * 32 + 255) / 256;
    const int GE = (NEDGES + 255) / 256;

    // ---- fork: prep chain on s2 || layer-0 GEMM on main stream ----
    cudaEventRecord(ev_fork, 0);
    cudaStreamWaitEvent(s2, ev_fork, 0);

    cudaMemsetAsync(p_deg, 0, NNODES * sizeof(int), s2);
    k_deg<<<GE, 256, 0, s2>>>(ei);
    k_scan1<<<NBLK, SCAN_B, 0, s2>>>();
    k_scan3<<<(NNODES + SCAN_B - 1) / SCAN_B, SCAN_B, 0, s2>>>();
    k_fill<<<GE, 256, 0, s2>>>(ei);
    cudaEventRecord(ev_join, s2);

    k_gemm_mma<256><<<GT, 512, SM256>>>(x, Wl0, Wr0, (__nv_bfloat162*)p_zb, (float*)p_y);

    // ---- join ----
    cudaStreamWaitEvent(0, ev_join, 0);

    // ---- layer 0 combine ----
    k_gather_combine128<<<GW, 256>>>((const uint2*)p_zb, (const float*)p_y, bl0, (float*)p_h);

    // ---- layer 1 ----
    k_gemm_mma<256><<<GT, 512, SM256>>>((const float*)p_h, Wl1, Wr1,
                                        (__nv_bfloat162*)p_zb, (float*)p_y);
    k_gather_combine128<<<GW, 256>>>((const uint2*)p_zb, (const float*)p_y, bl1, (float*)p_h);

    // ---- layer 2 + log_softmax ----
    k_gemm_mma<128><<<GT, 512, SM128>>>((const float*)p_h, Wl2, Wr2,
                                        (__nv_bfloat162*)p_zb, (float*)p_y);
    k_gather_final64<<<GW, 256>>>((const unsigned*)p_zb, (const float*)p_y, bl2, out);
}

// round 15
// speedup vs baseline: 1.2781x; 1.0061x over previous
#include <cuda_runtime.h>
#include <cuda_bf16.h>
#include <cstdint>

// ---------------- problem constants ----------------
#define NNODES 50000
#define NEDGES 800000
#define SCAN_B 256
#define NBLK   ((NNODES + SCAN_B - 1) / SCAN_B)   // 196

// ---------------- device scratch (no allocs allowed) ----------------
// NOTE: g_deg relies on zero-init at module load; every execution re-zeroes it
// in k_gather_final64 for the next replay (deterministic across graph replays).
__device__ int   g_deg[NNODES];
__device__ int   g_rowptr[NNODES + 1];
__device__ int   g_fill[NNODES];        // seeded to row start in scan3
__device__ int   g_csrc[NEDGES];
__device__ int   g_bsum[NBLK];
__device__ float g_dinv[NNODES];
__device__ uint2 g_zb[NNODES * 32];     // z bf16: 128 cols = 32 uint2
__device__ float g_y[NNODES * 128];
__device__ float g_h[NNODES * 128];

__device__ __forceinline__ uint32_t pack_bf2(float x, float y) {
    __nv_bfloat162 t = __float22bfloat162_rn(make_float2(x, y));
    return *(uint32_t*)&t;
}
__device__ __forceinline__ uint32_t smem_addr32(const void* p) {
    uint32_t a;
    asm("{ .reg .u64 t; cvta.to.shared.u64 t, %1; cvt.u32.u64 %0, t; }" : "=r"(a) : "l"(p));
    return a;
}
__device__ __forceinline__ void ldm_x4(uint32_t& r0, uint32_t& r1, uint32_t& r2, uint32_t& r3,
                                       uint32_t addr) {
    asm volatile("ldmatrix.sync.aligned.m8n8.x4.shared.b16 {%0,%1,%2,%3}, [%4];"
                 : "=r"(r0), "=r"(r1), "=r"(r2), "=r"(r3) : "r"(addr));
}
__device__ __forceinline__ bool edges_are_int32(const long long* e64) {
    bool is32 = false;
    #pragma unroll
    for (int q = 0; q < 4; ++q) {        // broadcast loads; uniform branch
        long long v = e64[q];
        if (v < 0 || v >= NNODES) is32 = true;
    }
    return is32;
}

// ---------------- degree: 4 edges/thread, int4 fast path ----------------
__global__ void k_deg(const void* __restrict__ ei_raw) {
    int t = blockIdx.x * blockDim.x + threadIdx.x;
    int i = t * 4;
    if (i >= NEDGES) return;
    const long long* e64 = (const long long*)ei_raw;
    if (edges_are_int32(e64)) {
        int4 d4 = ((const int4*)ei_raw)[t];
        atomicAdd(&g_deg[d4.x], 1);
        atomicAdd(&g_deg[d4.y], 1);
        atomicAdd(&g_deg[d4.z], 1);
        atomicAdd(&g_deg[d4.w], 1);
    } else {
        atomicAdd(&g_deg[(int)e64[i + 0]], 1);
        atomicAdd(&g_deg[(int)e64[i + 1]], 1);
        atomicAdd(&g_deg[(int)e64[i + 2]], 1);
        atomicAdd(&g_deg[(int)e64[i + 3]], 1);
    }
}

// ---------------- CSR scans ----------------
__global__ void k_scan1() {
    __shared__ int s[SCAN_B];
    int tid = threadIdx.x;
    int i = blockIdx.x * SCAN_B + tid;
    int v = (i < NNODES) ? g_deg[i] : 0;
    s[tid] = v;
    __syncthreads();
    #pragma unroll
    for (int off = 1; off < SCAN_B; off <<= 1) {
        int t = (tid >= off) ? s[tid - off] : 0;
        __syncthreads();
        s[tid] += t;
        __syncthreads();
    }
    if (i < NNODES) g_rowptr[i + 1] = s[tid];
    if (tid == SCAN_B - 1) g_bsum[blockIdx.x] = s[tid];
}

__global__ void k_scan3() {
    __shared__ int red[SCAN_B];
    int tid = threadIdx.x;
    int part = (tid < (int)blockIdx.x && tid < NBLK) ? g_bsum[tid] : 0;
    red[tid] = part;
    __syncthreads();
    #pragma unroll
    for (int off = SCAN_B / 2; off > 0; off >>= 1) {
        if (tid < off) red[tid] += red[tid + off];
        __syncthreads();
    }
    int offset = red[0];
    int i = blockIdx.x * SCAN_B + tid;
    if (i == 0) g_rowptr[0] = 0;
    if (i < NNODES) {
        int deg = g_deg[i];
        int end = g_rowptr[i + 1] + offset;
        g_rowptr[i + 1] = end;
        g_fill[i] = end - deg;                 // row start = fill cursor seed
        g_dinv[i] = 1.0f / fmaxf((float)deg, 1.0f);
    }
}

// ---------------- CSR fill: 4 edges/thread, cursor atomics ----------------
__global__ void k_fill(const void* __restrict__ ei_raw) {
    int t = blockIdx.x * blockDim.x + threadIdx.x;
    int i = t * 4;
    if (i >= NEDGES) return;
    const long long* e64 = (const long long*)ei_raw;
    int d0, d1, d2, d3, s0, s1, s2, s3;
    if (edges_are_int32(e64)) {
        int4 d4 = ((const int4*)ei_raw)[t];
        int4 s4 = ((const int4*)ei_raw)[NEDGES / 4 + t];
        d0 = d4.x; d1 = d4.y; d2 = d4.z; d3 = d4.w;
        s0 = s4.x; s1 = s4.y; s2 = s4.z; s3 = s4.w;
    } else {
        d0 = (int)e64[i + 0]; d1 = (int)e64[i + 1];
        d2 = (int)e64[i + 2]; d3 = (int)e64[i + 3];
        s0 = (int)e64[NEDGES + i + 0]; s1 = (int)e64[NEDGES + i + 1];
        s2 = (int)e64[NEDGES + i + 2]; s3 = (int)e64[NEDGES + i + 3];
    }
    int p0 = atomicAdd(&g_fill[d0], 1);
    int p1 = atomicAdd(&g_fill[d1], 1);
    int p2 = atomicAdd(&g_fill[d2], 1);
    int p3 = atomicAdd(&g_fill[d3], 1);
    g_csrc[p0] = s0;
    g_csrc[p1] = s1;
    g_csrc[p2] = s2;
    g_csrc[p3] = s3;
}

// ---------------- mma.sync bf16 m16n8k16 dual GEMM (ldmatrix loads) ------
template <int NC>
__global__ __launch_bounds__(512, 1)
void k_gemm_mma(const float* __restrict__ H,
                const float* __restrict__ Wl, const float* __restrict__ Wr,
                __nv_bfloat162* __restrict__ Zb, float* __restrict__ Y) {
    constexpr int D   = NC / 2;
    constexpr int NT  = NC / 32;        // n-frags per warp (8 / 4)
    constexpr int NP  = NT / 2;         // ldmatrix pairs   (4 / 2)
    constexpr int STU = 68;             // row stride in uint32

    extern __shared__ uint32_t smem[];
    uint32_t* sA = smem;                // 128 x STU
    uint32_t* sB = smem + 128 * STU;    // NC x STU

    const int tid  = threadIdx.x;
    const int wid  = tid >> 5;
    const int lane = tid & 31;
    const int row0 = blockIdx.x * 128;

    {
        const float4* h4 = (const float4*)H;
        #pragma unroll
        for (int i = tid; i < 128 * 32; i += 512) {
            int r = i >> 5, c = i & 31;
            int gr = row0 + r;
            float4 v = make_float4(0.f, 0.f, 0.f, 0.f);
            if (gr < NNODES) v = h4[gr * 32 + c];
            uint2 p = make_uint2(pack_bf2(v.x, v.y), pack_bf2(v.z, v.w));
            *(uint2*)&sA[r * STU + c * 2] = p;
        }
    }
    {
        #pragma unroll
        for (int i = tid; i < NC * 32; i += 512) {
            int n = i >> 5, c = i & 31;
            const float4* wsrc = (const float4*)((n < D) ? (Wl + n * 128)
                                                         : (Wr + (n - D) * 128));
            float4 v = wsrc[c];
            uint2 p = make_uint2(pack_bf2(v.x, v.y), pack_bf2(v.z, v.w));
            *(uint2*)&sB[n * STU + c * 2] = p;
        }
    }
    __syncthreads();

    const int warp_m = wid & 3;
    const int warp_n = wid >> 2;
    const int lm = lane >> 2;
    const int lk = lane & 3;

    const int lrow = (lane & 7) + ((lane >> 3) & 1) * 8;   // row within 16
    const int lkof = (lane >> 4) * 4;                      // 0 or 4 uint32
    const uint32_t sa32 = smem_addr32(sA);
    const uint32_t sb32 = smem_addr32(sB);

    float acc[2][NT][4];
    #pragma unroll
    for (int mi = 0; mi < 2; ++mi)
        #pragma unroll
        for (int ni = 0; ni < NT; ++ni)
            #pragma unroll
            for (int q = 0; q < 4; ++q) acc[mi][ni][q] = 0.f;

    #pragma unroll
    for (int kk = 0; kk < 8; ++kk) {
        const int k0u = kk * 8;
        uint32_t a[2][4];
        #pragma unroll
        for (int mi = 0; mi < 2; ++mi) {
            const int rb = warp_m * 32 + mi * 16;
            uint32_t ad = sa32 + (uint32_t)(((rb + lrow) * STU + k0u + lkof) * 4);
            ldm_x4(a[mi][0], a[mi][1], a[mi][2], a[mi][3], ad);
        }
        uint32_t b[NT][2];
        #pragma unroll
        for (int p = 0; p < NP; ++p) {
            const int nb = warp_n * (NT * 8) + p * 16;
            uint32_t bd = sb32 + (uint32_t)(((nb + lrow) * STU + k0u + lkof) * 4);
            ldm_x4(b[2 * p][0], b[2 * p + 1][0], b[2 * p][1], b[2 * p + 1][1], bd);
        }
        #pragma unroll
        for (int mi = 0; mi < 2; ++mi)
            #pragma unroll
            for (int ni = 0; ni < NT; ++ni) {
                asm volatile(
                    "mma.sync.aligned.m16n8k16.row.col.f32.bf16.bf16.f32 "
                    "{%0,%1,%2,%3}, {%4,%5,%6,%7}, {%8,%9}, {%0,%1,%2,%3};"
                    : "+f"(acc[mi][ni][0]), "+f"(acc[mi][ni][1]),
                      "+f"(acc[mi][ni][2]), "+f"(acc[mi][ni][3])
                    : "r"(a[mi][0]), "r"(a[mi][1]), "r"(a[mi][2]), "r"(a[mi][3]),
                      "r"(b[ni][0]), "r"(b[ni][1]));
            }
    }

    {
        const bool yhalf = (warp_n >= 2);
        const int cbase = warp_n * (NT * 8) - (yhalf ? D : 0);
        #pragma unroll
        for (int mi = 0; mi < 2; ++mi) {
            const int rl = row0 + warp_m * 32 + mi * 16 + lm;
            const int rh = rl + 8;
            #pragma unroll
            for (int ni = 0; ni < NT; ++ni) {
                const int oc = cbase + ni * 8 + lk * 2;
                if (yhalf) {
                    if (rl < NNODES)
                        *(float2*)&Y[rl * D + oc] = make_float2(acc[mi][ni][0], acc[mi][ni][1]);
                    if (rh < NNODES)
                        *(float2*)&Y[rh * D + oc] = make_float2(acc[mi][ni][2], acc[mi][ni][3]);
                } else {
                    if (rl < NNODES)
                        Zb[rl * (D / 2) + oc / 2] =
                            __float22bfloat162_rn(make_float2(acc[mi][ni][0], acc[mi][ni][1]));
                    if (rh < NNODES)
                        Zb[rh * (D / 2) + oc / 2] =
                            __float22bfloat162_rn(make_float2(acc[mi][ni][2], acc[mi][ni][3]));
                }
            }
        }
    }
}

// -------- gather + combine + relu (D=128): warp/node, 4-wide MLP ----------
__global__ __launch_bounds__(256)
void k_gather_combine128(const uint2* __restrict__ Zb, const float* __restrict__ Yb,
                         const float* __restrict__ bias, float* __restrict__ Hout) {
    const int w    = (blockIdx.x * blockDim.x + threadIdx.x) >> 5;
    const int lane = threadIdx.x & 31;
    if (w >= NNODES) return;
    int j = g_rowptr[w];
    const int e = g_rowptr[w + 1];
    float4 a0 = make_float4(0.f, 0.f, 0.f, 0.f);
    float4 a1 = make_float4(0.f, 0.f, 0.f, 0.f);
    float4 a2 = make_float4(0.f, 0.f, 0.f, 0.f);
    float4 a3 = make_float4(0.f, 0.f, 0.f, 0.f);
    for (; j + 3 < e; j += 4) {
        int s0 = g_csrc[j];
        int s1 = g_csrc[j + 1];
        int s2 = g_csrc[j + 2];
        int s3 = g_csrc[j + 3];
        uint2 u0 = Zb[s0 * 32 + lane];
        uint2 u1 = Zb[s1 * 32 + lane];
        uint2 u2 = Zb[s2 * 32 + lane];
        uint2 u3 = Zb[s3 * 32 + lane];
        float2 f;
        f = __bfloat1622float2(*(const __nv_bfloat162*)&u0.x); a0.x += f.x; a0.y += f.y;
        f = __bfloat1622float2(*(const __nv_bfloat162*)&u0.y); a0.z += f.x; a0.w += f.y;
        f = __bfloat1622float2(*(const __nv_bfloat162*)&u1.x); a1.x += f.x; a1.y += f.y;
        f = __bfloat1622float2(*(const __nv_bfloat162*)&u1.y); a1.z += f.x; a1.w += f.y;
        f = __bfloat1622float2(*(const __nv_bfloat162*)&u2.x); a2.x += f.x; a2.y += f.y;
        f = __bfloat1622float2(*(const __nv_bfloat162*)&u2.y); a2.z += f.x; a2.w += f.y;
        f = __bfloat1622float2(*(const __nv_bfloat162*)&u3.x); a3.x += f.x; a3.y += f.y;
        f = __bfloat1622float2(*(const __nv_bfloat162*)&u3.y); a3.z += f.x; a3.w += f.y;
    }
    for (; j < e; ++j) {
        int s0 = g_csrc[j];
        uint2 u0 = Zb[s0 * 32 + lane];
        float2 f;
        f = __bfloat1622float2(*(const __nv_bfloat162*)&u0.x); a0.x += f.x; a0.y += f.y;
        f = __bfloat1622float2(*(const __nv_bfloat162*)&u0.y); a0.z += f.x; a0.w += f.y;
    }
    a0.x += a1.x + a2.x + a3.x;
    a0.y += a1.y + a2.y + a3.y;
    a0.z += a1.z + a2.z + a3.z;
    a0.w += a1.w + a2.w + a3.w;
    float inv = g_dinv[w];
    float4 yv = ((const float4*)Yb)[w * 32 + lane];
    float4 bv = ((const float4*)bias)[lane];
    float4 o;
    o.x = fmaxf(a0.x * inv + yv.x + bv.x, 0.f);
    o.y = fmaxf(a0.y * inv + yv.y + bv.y, 0.f);
    o.z = fmaxf(a0.z * inv + yv.z + bv.z, 0.f);
    o.w = fmaxf(a0.w * inv + yv.w + bv.w, 0.f);
    ((float4*)Hout)[w * 32 + lane] = o;
}

// -------- gather + combine + log_softmax (D=64); also re-zeroes g_deg -----
__global__ __launch_bounds__(256)
void k_gather_final64(const unsigned* __restrict__ Zb, const float* __restrict__ Yb,
                      const float* __restrict__ bias, float* __restrict__ out) {
    // re-zero degree array for the next graph replay (deg unused after scan3)
    {
        const int gtid = blockIdx.x * blockDim.x + threadIdx.x;
        const int gsz  = gridDim.x * blockDim.x;
        for (int i = gtid; i < NNODES; i += gsz) g_deg[i] = 0;
    }
    const int w    = (blockIdx.x * blockDim.x + threadIdx.x) >> 5;
    const int lane = threadIdx.x & 31;
    if (w >= NNODES) return;
    int j = g_rowptr[w];
    const int e = g_rowptr[w + 1];
    float2 a0 = make_float2(0.f, 0.f);
    float2 a1 = make_float2(0.f, 0.f);
    float2 a2 = make_float2(0.f, 0.f);
    float2 a3 = make_float2(0.f, 0.f);
    for (; j + 3 < e; j += 4) {
        int s0 = g_csrc[j];
        int s1 = g_csrc[j + 1];
        int s2 = g_csrc[j + 2];
        int s3 = g_csrc[j + 3];
        unsigned u0 = Zb[s0 * 32 + lane];
        unsigned u1 = Zb[s1 * 32 + lane];
        unsigned u2 = Zb[s2 * 32 + lane];
        unsigned u3 = Zb[s3 * 32 + lane];
        float2 f;
        f = __bfloat1622float2(*(const __nv_bfloat162*)&u0); a0.x += f.x; a0.y += f.y;
        f = __bfloat1622float2(*(const __nv_bfloat162*)&u1); a1.x += f.x; a1.y += f.y;
        f = __bfloat1622float2(*(const __nv_bfloat162*)&u2); a2.x += f.x; a2.y += f.y;
        f = __bfloat1622float2(*(const __nv_bfloat162*)&u3); a3.x += f.x; a3.y += f.y;
    }
    for (; j < e; ++j) {
        int s0 = g_csrc[j];
        unsigned u0 = Zb[s0 * 32 + lane];
        float2 f = __bfloat1622float2(*(const __nv_bfloat162*)&u0);
        a0.x += f.x; a0.y += f.y;
    }
    a0.x += a1.x + a2.x + a3.x;
    a0.y += a1.y + a2.y + a3.y;
    float inv = g_dinv[w];
    float2 yv = ((const float2*)Yb)[w * 32 + lane];
    float2 bv = ((const float2*)bias)[lane];
    float v0 = a0.x * inv + yv.x + bv.x;
    float v1 = a0.y * inv + yv.y + bv.y;
    float m = fmaxf(v0, v1);
    #pragma unroll
    for (int o = 16; o; o >>= 1) m = fmaxf(m, __shfl_xor_sync(0xffffffffu, m, o));
    float s = expf(v0 - m) + expf(v1 - m);
    #pragma unroll
    for (int o = 16; o; o >>= 1) s += __shfl_xor_sync(0xffffffffu, s, o);
    float lse = m + logf(s);
    out[w * 64 + lane * 2 + 0] = v0 - lse;
    out[w * 64 + lane * 2 + 1] = v1 - lse;
}

// ---------------- host launch ----------------
extern "C" void kernel_launch(void* const* d_in, const int* in_sizes, int n_in,
                              void* d_out, int out_size) {
    const float* x   = (const float*)d_in[0];
    const void*  ei  = d_in[1];
    const float* Wl0 = (const float*)d_in[2];
    const float* bl0 = (const float*)d_in[3];
    const float* Wr0 = (const float*)d_in[4];
    const float* Wl1 = (const float*)d_in[5];
    const float* bl1 = (const float*)d_in[6];
    const float* Wr1 = (const float*)d_in[7];
    const float* Wl2 = (const float*)d_in[8];
    const float* bl2 = (const float*)d_in[9];
    const float* Wr2 = (const float*)d_in[10];
    float* out = (float*)d_out;
    (void)in_sizes; (void)n_in; (void)out_size;

    void *p_zb, *p_y, *p_h;
    cudaGetSymbolAddress(&p_zb, g_zb);
    cudaGetSymbolAddress(&p_y,  g_y);
    cudaGetSymbolAddress(&p_h,  g_h);

    static cudaStream_t s2 = nullptr;
    static cudaEvent_t  ev_fork = nullptr, ev_join = nullptr;
    if (!s2) {
        cudaStreamCreateWithFlags(&s2, cudaStreamNonBlocking);
        cudaEventCreateWithFlags(&ev_fork, cudaEventDisableTiming);
        cudaEventCreateWithFlags(&ev_join, cudaEventDisableTiming);
    }

    const int SM256 = (128 + 256) * 68 * 4;   // 104448
    const int SM128 = (128 + 128) * 68 * 4;   //  69632
    cudaFuncSetAttribute(k_gemm_mma<256>, cudaFuncAttributeMaxDynamicSharedMemorySize, SM256);
    cudaFuncSetAttribute(k_gemm_mma<128>, cudaFuncAttributeMaxDynamicSharedMemorySize, SM128);

    const int GT  = (NNODES + 127) / 128;
    const int GW  = (NNODES * 32 + 255) / 256;
    const int GE4 = (NEDGES / 4 + 255) / 256;   // 4 edges per thread

    // ---- fork: prep chain on s2 || layer-0 GEMM on main stream ----
    cudaEventRecord(ev_fork, 0);
    cudaStreamWaitEvent(s2, ev_fork, 0);

    k_deg<<<GE4, 256, 0, s2>>>(ei);
    k_scan1<<<NBLK, SCAN_B, 0, s2>>>();
    k_scan3<<<(NNODES + SCAN_B - 1) / SCAN_B, SCAN_B, 0, s2>>>();
    k_fill<<<GE4, 256, 0, s2>>>(ei);
    cudaEventRecord(ev_join, s2);

    k_gemm_mma<256><<<GT, 512, SM256>>>(x, Wl0, Wr0, (__nv_bfloat162*)p_zb, (float*)p_y);

    // ---- join ----
    cudaStreamWaitEvent(0, ev_join, 0);

    // ---- layer 0 combine ----
    k_gather_combine128<<<GW, 256>>>((const uint2*)p_zb, (const float*)p_y, bl0, (float*)p_h);

    // ---- layer 1 ----
    k_gemm_mma<256><<<GT, 512, SM256>>>((const float*)p_h, Wl1, Wr1,
                                        (__nv_bfloat162*)p_zb, (float*)p_y);
    k_gather_combine128<<<GW, 256>>>((const uint2*)p_zb, (const float*)p_y, bl1, (float*)p_h);

    // ---- layer 2 + log_softmax (re-zeroes g_deg for next replay) ----
    k_gemm_mma<128><<<GT, 512, SM128>>>((const float*)p_h, Wl2, Wr2,
                                        (__nv_bfloat162*)p_zb, (float*)p_y);
    k_gather_final64<<<GW, 256>>>((const unsigned*)p_zb, (const float*)p_y, bl2, out);
}